// round 2
// baseline (speedup 1.0000x reference)
#include <cuda_runtime.h>
#include <math.h>

#define ROWS 32768          // B*S
#define HD   768
#define KW   192            // HD/4 packed words
#define NTOT (ROWS*HD)

// ---------------- device scratch (static, allowed) ----------------
__device__ int      g_acc[NTOT];          // int32 GEMM acc -> q22 int -> out f32 (reused)
__device__ unsigned g_x8[ROWS*KW];        // packed int8 hidden activations
__device__ unsigned g_r8[ROWS*KW];        // packed int8 residual activations
__device__ unsigned g_w8[HD*KW];          // packed int8 weights [out][in/4]
__device__ float    g_bscale[HD], g_bint[HD];
__device__ double   g_Mb[HD], g_Ebp[HD];  // frexp consts for bias_scale/s22
__device__ double   g_M1, g_E1p;          // frexp consts for s_act/s22
__device__ float    g_biasint[HD], g_sfout[HD];
__device__ double   g_M2[HD], g_E2p[HD];  // frexp consts for sf_out/s8
__device__ float    g_s22, g_s8;
__device__ float    g_mean[ROWS];
__device__ unsigned g_red[4];             // umin22,umax22,umin8,umax8 (order-keys)
__device__ int      g_shift;

// order-preserving float<->uint key
__device__ __forceinline__ unsigned fkey(float f) {
    unsigned u = __float_as_uint(f);
    return (u & 0x80000000u) ? ~u : (u | 0x80000000u);
}
__device__ __forceinline__ float fdec(unsigned u) {
    return (u & 0x80000000u) ? __uint_as_float(u ^ 0x80000000u) : __uint_as_float(~u);
}

// ---------------- K_init: reset reduction scratch (graph replays) ----------------
__global__ void k_init() {
    g_red[0] = 0xFFFFFFFFu; g_red[1] = 0u;
    g_red[2] = 0xFFFFFFFFu; g_red[3] = 0u;
    g_shift = 0;
}

// ---------------- K_wq: per-output-channel weight quantization + pack ----------------
__global__ __launch_bounds__(256) void k_wq(const float* __restrict__ w,
                                            const float* __restrict__ bias,
                                            const float* __restrict__ sact) {
    __shared__ float smn[256], smx[256];
    __shared__ float sscale;
    int row = blockIdx.x, t = threadIdx.x;
    float mn = 1e30f, mx = -1e30f;
    for (int i = t; i < HD; i += 256) {
        float v = w[row*HD + i];
        mn = fminf(mn, v); mx = fmaxf(mx, v);
    }
    smn[t] = mn; smx[t] = mx; __syncthreads();
    for (int s = 128; s > 0; s >>= 1) {
        if (t < s) { smn[t] = fminf(smn[t], smn[t+s]); smx[t] = fmaxf(smx[t], smx[t+s]); }
        __syncthreads();
    }
    if (t == 0) {
        float v = fmaxf(fmaxf(fabsf(smn[0]), fabsf(smx[0])), 1e-8f);
        float sc = v / 127.0f;
        sscale = sc;
        float bs = sc * sact[0];
        g_bscale[row] = bs;
        float bi = rintf(bias[row] / bs);
        bi = fminf(fmaxf(bi, -2147483647.0f), 2147483646.0f);
        g_bint[row] = bi;
    }
    __syncthreads();
    float sc = sscale;
    if (t < KW) {
        unsigned word = 0;
        #pragma unroll
        for (int b = 0; b < 4; b++) {
            float q = rintf(w[row*HD + 4*t + b] / sc);
            q = fminf(fmaxf(q, -127.0f), 126.0f);
            int qi = (int)q;
            word |= ((unsigned)(qi & 0xFF)) << (8*b);
        }
        g_w8[row*KW + t] = word;
    }
}

// ---------------- K_pack: quantize/pack activations to int8 ----------------
__global__ __launch_bounds__(256) void k_pack(const float* __restrict__ hs, const float* __restrict__ s1p,
                                              const float* __restrict__ rs, const float* __restrict__ s2p) {
    int i = blockIdx.x * 256 + threadIdx.x;
    if (i >= ROWS*KW) return;
    float s1 = s1p[0], s2 = s2p[0];
    float4 hv = ((const float4*)hs)[i];
    float4 rv = ((const float4*)rs)[i];
    unsigned wa = 0, wb = 0;
    int q;
    q = __float2int_rn(hv.x/s1); wa |= (unsigned)(q & 0xFF);
    q = __float2int_rn(hv.y/s1); wa |= (unsigned)(q & 0xFF) << 8;
    q = __float2int_rn(hv.z/s1); wa |= (unsigned)(q & 0xFF) << 16;
    q = __float2int_rn(hv.w/s1); wa |= (unsigned)(q & 0xFF) << 24;
    q = __float2int_rn(rv.x/s2); wb |= (unsigned)(q & 0xFF);
    q = __float2int_rn(rv.y/s2); wb |= (unsigned)(q & 0xFF) << 8;
    q = __float2int_rn(rv.z/s2); wb |= (unsigned)(q & 0xFF) << 16;
    q = __float2int_rn(rv.w/s2); wb |= (unsigned)(q & 0xFF) << 24;
    g_x8[i] = wa; g_r8[i] = wb;
}

// ---------------- K_gemm: 64x64 tiled dp4a GEMM + fused x_act min/max ----------------
__global__ __launch_bounds__(256) void k_gemm(const float* __restrict__ insf) {
    __shared__ unsigned As[64][17];
    __shared__ unsigned Bs[64][17];
    __shared__ float sred[512];
    int tid = threadIdx.x;
    int ty = tid >> 4, tx = tid & 15;
    int m0 = blockIdx.y * 64, n0 = blockIdx.x * 64;
    int acc[4][4];
    #pragma unroll
    for (int i = 0; i < 4; i++)
        #pragma unroll
        for (int j = 0; j < 4; j++) acc[i][j] = 0;

    int lr = tid >> 2, lc = (tid & 3) * 4;
    for (int kt = 0; kt < 12; kt++) {
        uint4 av = *(const uint4*)&g_x8[(m0 + lr)*KW + kt*16 + lc];
        uint4 bv = *(const uint4*)&g_w8[(n0 + lr)*KW + kt*16 + lc];
        As[lr][lc+0] = av.x; As[lr][lc+1] = av.y; As[lr][lc+2] = av.z; As[lr][lc+3] = av.w;
        Bs[lr][lc+0] = bv.x; Bs[lr][lc+1] = bv.y; Bs[lr][lc+2] = bv.z; Bs[lr][lc+3] = bv.w;
        __syncthreads();
        #pragma unroll
        for (int kk = 0; kk < 16; kk++) {
            int a[4], b[4];
            #pragma unroll
            for (int i = 0; i < 4; i++) a[i] = (int)As[ty*4+i][kk];
            #pragma unroll
            for (int j = 0; j < 4; j++) b[j] = (int)Bs[tx*4+j][kk];
            #pragma unroll
            for (int i = 0; i < 4; i++)
                #pragma unroll
                for (int j = 0; j < 4; j++)
                    acc[i][j] = __dp4a(a[i], b[j], acc[i][j]);
        }
        __syncthreads();
    }
    // epilogue: store acc, track min/max of x_act = (acc+b_int)*bscale + s_act*r
    float sa = insf[0];
    float bsv[4], biv[4];
    #pragma unroll
    for (int j = 0; j < 4; j++) { int n = n0 + tx*4 + j; bsv[j] = g_bscale[n]; biv[j] = g_bint[n]; }
    float mnl = 1e30f, mxl = -1e30f;
    #pragma unroll
    for (int i = 0; i < 4; i++) {
        int m = m0 + ty*4 + i;
        unsigned rw = g_r8[m*KW + (n0 >> 2) + tx];
        #pragma unroll
        for (int j = 0; j < 4; j++) {
            float hsv = ((float)acc[i][j] + biv[j]) * bsv[j];
            int rb = (int)(signed char)((rw >> (8*j)) & 0xFF);
            float xa = hsv + sa * (float)rb;
            mnl = fminf(mnl, xa); mxl = fmaxf(mxl, xa);
        }
        *(int4*)&g_acc[m*HD + n0 + tx*4] = make_int4(acc[i][0], acc[i][1], acc[i][2], acc[i][3]);
    }
    sred[tid] = mnl; sred[256 + tid] = mxl; __syncthreads();
    for (int s = 128; s > 0; s >>= 1) {
        if (tid < s) {
            sred[tid] = fminf(sred[tid], sred[tid+s]);
            sred[256+tid] = fmaxf(sred[256+tid], sred[256+tid+s]);
        }
        __syncthreads();
    }
    if (tid == 0) {
        atomicMin(&g_red[0], fkey(sred[0]));
        atomicMax(&g_red[1], fkey(sred[256]));
    }
}

// ---------------- K_prep22: s22 + per-channel frexp consts + LN consts ----------------
__global__ __launch_bounds__(768) void k_prep22(const float* __restrict__ insf,
                                                const float* __restrict__ lnw,
                                                const float* __restrict__ lnb) {
    __shared__ float s22sh;
    int t = threadIdx.x;
    if (t == 0) {
        float mn = fdec(g_red[0]), mx = fdec(g_red[1]);
        float v = fmaxf(fmaxf(fabsf(mn), fabsf(mx)), 1e-8f);
        float s = v / 2097151.0f;
        g_s22 = s; s22sh = s;
    }
    __syncthreads();
    double z = (double)s22sh;
    {
        double d = (double)g_bscale[t] / z;
        int ex; double mant = frexp(d, &ex);
        g_Mb[t]  = floor(mant * 2147483648.0 + 0.5);
        g_Ebp[t] = scalbn(1.0, ex - 31);
    }
    if (t == 0) {
        double d = (double)insf[0] / z;
        int ex; double mant = frexp(d, &ex);
        g_M1  = floor(mant * 2147483648.0 + 0.5);
        g_E1p = scalbn(1.0, ex - 31);
    }
    float sf = sqrtf(768.0f) / 1073741824.0f;
    g_biasint[t] = floorf((lnb[t] / lnw[t]) / sf);
    g_sfout[t]   = sf * lnw[t];
}

// ---------------- K_ln1: q22 + row mean + var0 + global shift ----------------
__global__ __launch_bounds__(256) void k_ln1() {
    __shared__ float  qsh[HD];
    __shared__ double rbuf[256];
    __shared__ double mish;
    int row = blockIdx.x, t = threadIdx.x;
    float s22 = g_s22;
    double lsum = 0.0;
    #pragma unroll
    for (int e = 0; e < 3; e++) {
        int c = t + e*256;
        int idx = row*HD + c;
        int a = g_acc[idx];
        float hs32 = ((float)a + g_bint[c]) * g_bscale[c];
        double zv = rint((double)hs32 / (double)g_bscale[c]);
        double p = rint((zv * g_Mb[c]) * g_Ebp[c]);
        unsigned rw = g_r8[row*KW + (c >> 2)];
        int rb = (int)(signed char)((rw >> ((c & 3)*8)) & 0xFF);
        p += rint(((double)rb * g_M1) * g_E1p);
        p = fmin(fmax(p, -2097152.0), 2097151.0);
        qsh[c] = (float)p;
        g_acc[idx] = (int)p;
        float xi = ((float)p * s22) / s22;
        lsum += (double)xi;
    }
    rbuf[t] = lsum; __syncthreads();
    for (int s = 128; s > 0; s >>= 1) { if (t < s) rbuf[t] += rbuf[t+s]; __syncthreads(); }
    if (t == 0) {
        double mi = rint(rbuf[0] / 768.0);
        mish = mi;
        g_mean[row] = (float)mi;
    }
    __syncthreads();
    float mi = (float)mish;
    double vsum = 0.0;
    #pragma unroll
    for (int e = 0; e < 3; e++) {
        int c = t + e*256;
        float xi = (qsh[c] * s22) / s22;
        float y = xi - mi;
        vsum += (double)y * (double)y;
    }
    rbuf[t] = vsum; __syncthreads();
    for (int s = 128; s > 0; s >>= 1) { if (t < s) rbuf[t] += rbuf[t+s]; __syncthreads(); }
    if (t == 0) {
        float vf = (float)rbuf[0];
        float sh = ceilf(log2f(sqrtf(fmaxf(vf, 1.0f) / 4294967296.0f)));
        atomicMax(&g_shift, (int)sh);
    }
}

// ---------------- K_ln2: normalize + out min/max ----------------
__global__ __launch_bounds__(256) void k_ln2() {
    __shared__ float ybuf[HD];
    __shared__ double rbuf[256];
    __shared__ float fach;
    int row = blockIdx.x, t = threadIdx.x;
    float s22 = g_s22;
    int shift = g_shift;
    float pshf = exp2f(-(float)shift);
    float mi = g_mean[row];
    double vsum = 0.0;
    #pragma unroll
    for (int e = 0; e < 3; e++) {
        int c = t + e*256;
        int q = g_acc[row*HD + c];
        float xi = (((float)q) * s22) / s22;
        float y = xi - mi;
        ybuf[c] = y;
        float ys = floorf(y * pshf);
        vsum += (double)ys * (double)ys;
    }
    rbuf[t] = vsum; __syncthreads();
    for (int s = 128; s > 0; s >>= 1) { if (t < s) rbuf[t] += rbuf[t+s]; __syncthreads(); }
    if (t == 0) {
        float varf = (float)rbuf[0];
        float stdv = floorf(sqrtf(varf)) * exp2f((float)shift);
        fach = floorf(2147483648.0f / stdv);
    }
    __syncthreads();
    float fac = fach;
    float mnl = 1e30f, mxl = -1e30f;
    #pragma unroll
    for (int e = 0; e < 3; e++) {
        int c = t + e*256;
        float y = ybuf[c];
        float y2 = floorf((y * fac) * 0.5f);
        y2 += g_biasint[c];
        float outv = y2 * g_sfout[c];
        ((float*)g_acc)[row*HD + c] = outv;
        mnl = fminf(mnl, outv); mxl = fmaxf(mxl, outv);
    }
    // reuse rbuf for float min/max reductions
    rbuf[t] = (double)mnl; __syncthreads();
    for (int s = 128; s > 0; s >>= 1) { if (t < s) rbuf[t] = fmin(rbuf[t], rbuf[t+s]); __syncthreads(); }
    double mnb = rbuf[0]; __syncthreads();
    rbuf[t] = (double)mxl; __syncthreads();
    for (int s = 128; s > 0; s >>= 1) { if (t < s) rbuf[t] = fmax(rbuf[t], rbuf[t+s]); __syncthreads(); }
    if (t == 0) {
        atomicMin(&g_red[2], fkey((float)mnb));
        atomicMax(&g_red[3], fkey((float)rbuf[0]));
    }
}

// ---------------- K_prep8: s8 + per-channel frexp consts ----------------
__global__ __launch_bounds__(768) void k_prep8(float* __restrict__ dout, int wscale) {
    __shared__ float s8sh;
    int t = threadIdx.x;
    if (t == 0) {
        float mn = fdec(g_red[2]), mx = fdec(g_red[3]);
        float v = fmaxf(fmaxf(fabsf(mn), fabsf(mx)), 1e-8f);
        float s = v / 127.0f;
        g_s8 = s; s8sh = s;
        if (wscale) dout[NTOT] = s;
    }
    __syncthreads();
    double d = (double)g_sfout[t] / (double)s8sh;
    int ex; double mant = frexp(d, &ex);
    g_M2[t]  = floor(mant * 2147483648.0 + 0.5);
    g_E2p[t] = scalbn(1.0, ex - 31);
}

// ---------------- K_final: 8-bit requantization ----------------
__global__ __launch_bounds__(256) void k_final(float* __restrict__ dout) {
    int i = blockIdx.x * 256 + threadIdx.x;
    if (i >= NTOT/4) return;
    float s8 = g_s8;
    const float* gaf = (const float*)g_acc;
    float4 v = ((const float4*)gaf)[i];
    int c0 = (i * 4) % HD;
    float o[4]; float vv[4] = {v.x, v.y, v.z, v.w};
    #pragma unroll
    for (int j = 0; j < 4; j++) {
        int c = c0 + j;
        double z = rint((double)vv[j] / (double)g_sfout[c]);
        double p = rint((z * g_M2[c]) * g_E2p[c]);
        p = fmin(fmax(p, -128.0), 127.0);
        o[j] = (float)p * s8;
    }
    ((float4*)dout)[i] = make_float4(o[0], o[1], o[2], o[3]);
}

// ---------------- launch ----------------
extern "C" void kernel_launch(void* const* d_in, const int* in_sizes, int n_in,
                              void* d_out, int out_size) {
    const float* hs   = (const float*)d_in[0];
    const float* hssf = (const float*)d_in[1];
    const float* inp  = (const float*)d_in[2];
    const float* insf = (const float*)d_in[3];
    const float* w    = (const float*)d_in[4];
    const float* bias = (const float*)d_in[5];
    const float* lnw  = (const float*)d_in[6];
    const float* lnb  = (const float*)d_in[7];
    float* dout = (float*)d_out;

    k_init<<<1, 1>>>();
    k_wq<<<HD, 256>>>(w, bias, hssf);
    k_pack<<<(ROWS*KW + 255)/256, 256>>>(hs, hssf, inp, insf);
    k_gemm<<<dim3(HD/64, ROWS/64), 256>>>(insf);
    k_prep22<<<1, 768>>>(insf, lnw, lnb);
    k_ln1<<<ROWS, 256>>>();
    k_ln2<<<ROWS, 256>>>();
    k_prep8<<<1, 768>>>(dout, out_size > NTOT ? 1 : 0);
    k_final<<<(NTOT/4 + 255)/256, 256>>>(dout);
}

// round 6
// speedup vs baseline: 5.0177x; 5.0177x over previous
#include <cuda_runtime.h>
#include <math.h>

#define ROWS 32768          // B*S
#define HD   768
#define KW   192            // HD/4 packed words
#define NTOT (ROWS*HD)

// ---------------- device scratch ----------------
__device__ int       g_acc[NTOT];          // int32 acc -> q22 int -> y_final int (reused)
__device__ unsigned  g_x8[ROWS*KW];
__device__ unsigned  g_r8[ROWS*KW];
__device__ unsigned  g_w8[HD*KW];
__device__ float     g_bscale[HD], g_bint[HD];
__device__ int       g_binti[HD];
__device__ long long g_Mbi[HD];
__device__ int       g_Ebi[HD];
__device__ long long g_M1i;
__device__ int       g_E1i;
__device__ int       g_biasint[HD];
__device__ float     g_sfout[HD];
__device__ long long g_M2i[HD];
__device__ int       g_E2i[HD];
__device__ float     g_s22, g_s8;
__device__ int       g_meani[ROWS];
__device__ unsigned  g_red[4];             // umin22,umax22,umin8,umax8
__device__ int       g_shift;

// order-preserving float<->uint key
__device__ __forceinline__ unsigned fkey(float f) {
    unsigned u = __float_as_uint(f);
    return (u & 0x80000000u) ? ~u : (u | 0x80000000u);
}
__device__ __forceinline__ float fdec(unsigned u) {
    return (u & 0x80000000u) ? __uint_as_float(u ^ 0x80000000u) : __uint_as_float(~u);
}

// round-half-even of t / 2^E  (E >= 1), exact integer version of rint((t)*2^-E)
__device__ __forceinline__ long long rhe(long long t, int E) {
    long long q = t >> E;                 // floor
    long long r = t - (q << E);           // remainder in [0, 2^E)
    long long half = 1LL << (E - 1);
    if (r > half)       q += 1;
    else if (r == half) q += (q & 1LL);   // ties to even
    return q;
}

// ---------------- K_init ----------------
__global__ void k_init() {
    g_red[0] = 0xFFFFFFFFu; g_red[1] = 0u;
    g_red[2] = 0xFFFFFFFFu; g_red[3] = 0u;
    g_shift = 0;
}

// ---------------- K_wq: per-output-channel weight quantization + pack ----------------
__global__ __launch_bounds__(256) void k_wq(const float* __restrict__ w,
                                            const float* __restrict__ bias,
                                            const float* __restrict__ sact) {
    __shared__ float smn[256], smx[256];
    __shared__ float sscale;
    int row = blockIdx.x, t = threadIdx.x;
    float mn = 1e30f, mx = -1e30f;
    for (int i = t; i < HD; i += 256) {
        float v = w[row*HD + i];
        mn = fminf(mn, v); mx = fmaxf(mx, v);
    }
    smn[t] = mn; smx[t] = mx; __syncthreads();
    for (int s = 128; s > 0; s >>= 1) {
        if (t < s) { smn[t] = fminf(smn[t], smn[t+s]); smx[t] = fmaxf(smx[t], smx[t+s]); }
        __syncthreads();
    }
    if (t == 0) {
        float v = fmaxf(fmaxf(fabsf(smn[0]), fabsf(smx[0])), 1e-8f);
        float sc = v / 127.0f;
        sscale = sc;
        float bs = sc * sact[0];
        g_bscale[row] = bs;
        float bi = rintf(bias[row] / bs);
        bi = fminf(fmaxf(bi, -2147483647.0f), 2147483646.0f);
        g_bint[row] = bi;
        g_binti[row] = (int)bi;
    }
    __syncthreads();
    float sc = sscale;
    if (t < KW) {
        unsigned word = 0;
        #pragma unroll
        for (int b = 0; b < 4; b++) {
            float q = rintf(w[row*HD + 4*t + b] / sc);
            q = fminf(fmaxf(q, -127.0f), 126.0f);
            int qi = (int)q;
            word |= ((unsigned)(qi & 0xFF)) << (8*b);
        }
        g_w8[row*KW + t] = word;
    }
}

// ---------------- K_pack ----------------
__global__ __launch_bounds__(256) void k_pack(const float* __restrict__ hs, const float* __restrict__ s1p,
                                              const float* __restrict__ rs, const float* __restrict__ s2p) {
    int i = blockIdx.x * 256 + threadIdx.x;
    if (i >= ROWS*KW) return;
    float s1 = s1p[0], s2 = s2p[0];
    float4 hv = ((const float4*)hs)[i];
    float4 rv = ((const float4*)rs)[i];
    unsigned wa = 0, wb = 0;
    int q;
    q = __float2int_rn(hv.x/s1); wa |= (unsigned)(q & 0xFF);
    q = __float2int_rn(hv.y/s1); wa |= (unsigned)(q & 0xFF) << 8;
    q = __float2int_rn(hv.z/s1); wa |= (unsigned)(q & 0xFF) << 16;
    q = __float2int_rn(hv.w/s1); wa |= (unsigned)(q & 0xFF) << 24;
    q = __float2int_rn(rv.x/s2); wb |= (unsigned)(q & 0xFF);
    q = __float2int_rn(rv.y/s2); wb |= (unsigned)(q & 0xFF) << 8;
    q = __float2int_rn(rv.z/s2); wb |= (unsigned)(q & 0xFF) << 16;
    q = __float2int_rn(rv.w/s2); wb |= (unsigned)(q & 0xFF) << 24;
    g_x8[i] = wa; g_r8[i] = wb;
}

// ---------------- K_gemm: 64x64 tiles, smem transposed [kk][row] for LDS.128 ----------------
__global__ __launch_bounds__(256) void k_gemm(const float* __restrict__ insf) {
    __shared__ unsigned As[16][68];   // [k-word][row], 68 keeps 16B alignment + pad
    __shared__ unsigned Bs[16][68];
    __shared__ float sred[512];
    int tid = threadIdx.x;
    int ty = tid >> 4, tx = tid & 15;
    int m0 = blockIdx.y * 64, n0 = blockIdx.x * 64;
    int acc[4][4];
    #pragma unroll
    for (int i = 0; i < 4; i++)
        #pragma unroll
        for (int j = 0; j < 4; j++) acc[i][j] = 0;

    int lr = tid >> 2, lc = (tid & 3) * 4;
    const unsigned* aptr = &g_x8[(m0 + lr)*KW + lc];
    const unsigned* bptr = &g_w8[(n0 + lr)*KW + lc];

    for (int kt = 0; kt < 12; kt++) {
        uint4 av = *(const uint4*)(aptr + kt*16);
        uint4 bv = *(const uint4*)(bptr + kt*16);
        __syncthreads();
        As[lc+0][lr] = av.x; As[lc+1][lr] = av.y; As[lc+2][lr] = av.z; As[lc+3][lr] = av.w;
        Bs[lc+0][lr] = bv.x; Bs[lc+1][lr] = bv.y; Bs[lc+2][lr] = bv.z; Bs[lc+3][lr] = bv.w;
        __syncthreads();
        #pragma unroll
        for (int kk = 0; kk < 16; kk++) {
            uint4 a4 = *(const uint4*)&As[kk][ty*4];
            uint4 b4 = *(const uint4*)&Bs[kk][tx*4];
            int a[4] = {(int)a4.x, (int)a4.y, (int)a4.z, (int)a4.w};
            int b[4] = {(int)b4.x, (int)b4.y, (int)b4.z, (int)b4.w};
            #pragma unroll
            for (int i = 0; i < 4; i++)
                #pragma unroll
                for (int j = 0; j < 4; j++)
                    acc[i][j] = __dp4a(a[i], b[j], acc[i][j]);
        }
    }
    // epilogue: store acc, track min/max of x_act = (acc+b_int)*bscale + s_act*r
    float sa = insf[0];
    float bsv[4], biv[4];
    #pragma unroll
    for (int j = 0; j < 4; j++) { int n = n0 + tx*4 + j; bsv[j] = g_bscale[n]; biv[j] = g_bint[n]; }
    float mnl = 1e30f, mxl = -1e30f;
    #pragma unroll
    for (int i = 0; i < 4; i++) {
        int m = m0 + ty*4 + i;
        unsigned rw = g_r8[m*KW + (n0 >> 2) + tx];
        #pragma unroll
        for (int j = 0; j < 4; j++) {
            float hsv = ((float)acc[i][j] + biv[j]) * bsv[j];
            int rb = (int)(signed char)((rw >> (8*j)) & 0xFF);
            float xa = hsv + sa * (float)rb;
            mnl = fminf(mnl, xa); mxl = fmaxf(mxl, xa);
        }
        *(int4*)&g_acc[m*HD + n0 + tx*4] = make_int4(acc[i][0], acc[i][1], acc[i][2], acc[i][3]);
    }
    sred[tid] = mnl; sred[256 + tid] = mxl; __syncthreads();
    for (int s = 128; s > 0; s >>= 1) {
        if (tid < s) {
            sred[tid] = fminf(sred[tid], sred[tid+s]);
            sred[256+tid] = fmaxf(sred[256+tid], sred[256+tid+s]);
        }
        __syncthreads();
    }
    if (tid == 0) {
        atomicMin(&g_red[0], fkey(sred[0]));
        atomicMax(&g_red[1], fkey(sred[256]));
    }
}

// ---------------- K_prep22: s22 + integer frexp consts + LN consts ----------------
__global__ __launch_bounds__(768) void k_prep22(const float* __restrict__ insf,
                                                const float* __restrict__ lnw,
                                                const float* __restrict__ lnb) {
    __shared__ float s22sh;
    int t = threadIdx.x;
    if (t == 0) {
        float mn = fdec(g_red[0]), mx = fdec(g_red[1]);
        float v = fmaxf(fmaxf(fabsf(mn), fabsf(mx)), 1e-8f);
        float s = v / 2097151.0f;
        g_s22 = s; s22sh = s;
    }
    __syncthreads();
    double z = (double)s22sh;
    {
        double d = (double)g_bscale[t] / z;
        int ex; double mant = frexp(d, &ex);
        g_Mbi[t] = (long long)floor(mant * 2147483648.0 + 0.5);
        g_Ebi[t] = 31 - ex;
    }
    if (t == 0) {
        double d = (double)insf[0] / z;
        int ex; double mant = frexp(d, &ex);
        g_M1i = (long long)floor(mant * 2147483648.0 + 0.5);
        g_E1i = 31 - ex;
    }
    float sf = sqrtf(768.0f) / 1073741824.0f;
    g_biasint[t] = (int)floorf((lnb[t] / lnw[t]) / sf);
    g_sfout[t]   = sf * lnw[t];
}

// ---------------- warp reduce helpers ----------------
__device__ __forceinline__ int wredAddI(int v) {
    #pragma unroll
    for (int o = 16; o > 0; o >>= 1) v += __shfl_down_sync(0xFFFFFFFFu, v, o);
    return v;
}
__device__ __forceinline__ long long wredAddLL(long long v) {
    #pragma unroll
    for (int o = 16; o > 0; o >>= 1) v += __shfl_down_sync(0xFFFFFFFFu, v, o);
    return v;
}
__device__ __forceinline__ float wredMinF(float v) {
    #pragma unroll
    for (int o = 16; o > 0; o >>= 1) v = fminf(v, __shfl_down_sync(0xFFFFFFFFu, v, o));
    return v;
}
__device__ __forceinline__ float wredMaxF(float v) {
    #pragma unroll
    for (int o = 16; o > 0; o >>= 1) v = fmaxf(v, __shfl_down_sync(0xFFFFFFFFu, v, o));
    return v;
}

// ---------------- K_ln1: integer q22 + row mean + var0 + global shift ----------------
__global__ __launch_bounds__(256) void k_ln1() {
    __shared__ int  smi[8];
    __shared__ long long sml[8];
    __shared__ int  s_mean;
    int row = blockIdx.x, t = threadIdx.x;
    int base = row*HD;
    int p[3];
    int sum = 0;
    #pragma unroll
    for (int e = 0; e < 3; e++) {
        int c = t + e*256;
        int a = g_acc[base + c];
        long long zv = (long long)a + (long long)g_binti[c];
        long long p1 = rhe(zv * g_Mbi[c], g_Ebi[c]);
        unsigned rw = g_r8[row*KW + (c >> 2)];
        int rb = (int)(signed char)((rw >> ((c & 3)*8)) & 0xFF);
        long long p2 = rhe((long long)rb * g_M1i, g_E1i);
        long long pp = p1 + p2;
        pp = pp < -2097152LL ? -2097152LL : (pp > 2097151LL ? 2097151LL : pp);
        p[e] = (int)pp;
        g_acc[base + c] = (int)pp;
        sum += p[e];
    }
    int ws = wredAddI(sum);
    if ((t & 31) == 0) smi[t >> 5] = ws;
    __syncthreads();
    if (t == 0) {
        int tot = 0;
        #pragma unroll
        for (int i = 0; i < 8; i++) tot += smi[i];
        int mi = (int)rint((double)tot / 768.0);
        s_mean = mi;
        g_meani[row] = mi;
    }
    __syncthreads();
    int mi = s_mean;
    long long vs = 0;
    #pragma unroll
    for (int e = 0; e < 3; e++) {
        long long y = (long long)(p[e] - mi);
        vs += y*y;
    }
    long long wv = wredAddLL(vs);
    if ((t & 31) == 0) sml[t >> 5] = wv;
    __syncthreads();
    if (t == 0) {
        long long var0 = 0;
        #pragma unroll
        for (int i = 0; i < 8; i++) var0 += sml[i];
        double v = (double)var0; if (v < 1.0) v = 1.0;
        double sh = ceil(log2(sqrt(v / 4294967296.0)));
        atomicMax(&g_shift, (int)sh);
    }
}

// ---------------- K_ln2: integer normalize + out min/max ----------------
__global__ __launch_bounds__(256) void k_ln2() {
    __shared__ long long sml[8];
    __shared__ long long s_fac;
    __shared__ float smn[8], smx[8];
    int row = blockIdx.x, t = threadIdx.x;
    int base = row*HD;
    int shift = g_shift;
    int mi = g_meani[row];
    int y[3];
    long long vsum = 0;
    #pragma unroll
    for (int e = 0; e < 3; e++) {
        int c = t + e*256;
        int q = g_acc[base + c];
        y[e] = q - mi;
        long long ys = (long long)(y[e] >> shift);   // arithmetic shift == floor
        vsum += ys*ys;
    }
    long long wv = wredAddLL(vsum);
    if ((t & 31) == 0) sml[t >> 5] = wv;
    __syncthreads();
    if (t == 0) {
        long long var_int = 0;
        #pragma unroll
        for (int i = 0; i < 8; i++) var_int += sml[i];
        double stdv = floor(sqrt((double)var_int)) * exp2((double)shift);
        s_fac = (long long)floor(2147483648.0 / stdv);
    }
    __syncthreads();
    long long fac = s_fac;
    float mnl = 1e30f, mxl = -1e30f;
    #pragma unroll
    for (int e = 0; e < 3; e++) {
        int c = t + e*256;
        long long y2 = ((long long)y[e] * fac) >> 1;   // floor(y*factor/2)
        int yfin = (int)(y2 + (long long)g_biasint[c]);
        g_acc[base + c] = yfin;
        float outv = (float)yfin * g_sfout[c];
        mnl = fminf(mnl, outv); mxl = fmaxf(mxl, outv);
    }
    float wmn = wredMinF(mnl), wmx = wredMaxF(mxl);
    if ((t & 31) == 0) { smn[t >> 5] = wmn; smx[t >> 5] = wmx; }
    __syncthreads();
    if (t == 0) {
        float m0 = 1e30f, m1 = -1e30f;
        #pragma unroll
        for (int i = 0; i < 8; i++) { m0 = fminf(m0, smn[i]); m1 = fmaxf(m1, smx[i]); }
        atomicMin(&g_red[2], fkey(m0));
        atomicMax(&g_red[3], fkey(m1));
    }
}

// ---------------- K_prep8 ----------------
__global__ __launch_bounds__(768) void k_prep8(float* __restrict__ dout, int wscale) {
    __shared__ float s8sh;
    int t = threadIdx.x;
    if (t == 0) {
        float mn = fdec(g_red[2]), mx = fdec(g_red[3]);
        float v = fmaxf(fmaxf(fabsf(mn), fabsf(mx)), 1e-8f);
        float s = v / 127.0f;
        g_s8 = s; s8sh = s;
        if (wscale) dout[NTOT] = s;
    }
    __syncthreads();
    double d = (double)g_sfout[t] / (double)s8sh;
    int ex; double mant = frexp(d, &ex);
    g_M2i[t] = (long long)floor(mant * 2147483648.0 + 0.5);
    g_E2i[t] = 31 - ex;
}

// ---------------- K_final: integer 8-bit requantization ----------------
__global__ __launch_bounds__(256) void k_final(float* __restrict__ dout) {
    int i = blockIdx.x * 256 + threadIdx.x;
    if (i >= NTOT/4) return;
    float s8 = g_s8;
    int4 v = ((const int4*)g_acc)[i];
    int c0 = (i * 4) % HD;
    int vv[4] = {v.x, v.y, v.z, v.w};
    float o[4];
    #pragma unroll
    for (int j = 0; j < 4; j++) {
        int c = c0 + j;
        long long tt = (long long)vv[j] * g_M2i[c];
        long long p = rhe(tt, g_E2i[c]);
        p = p < -128LL ? -128LL : (p > 127LL ? 127LL : p);
        o[j] = (float)p * s8;
    }
    ((float4*)dout)[i] = make_float4(o[0], o[1], o[2], o[3]);
}

// ---------------- launch ----------------
extern "C" void kernel_launch(void* const* d_in, const int* in_sizes, int n_in,
                              void* d_out, int out_size) {
    const float* hs   = (const float*)d_in[0];
    const float* hssf = (const float*)d_in[1];
    const float* inp  = (const float*)d_in[2];
    const float* insf = (const float*)d_in[3];
    const float* w    = (const float*)d_in[4];
    const float* bias = (const float*)d_in[5];
    const float* lnw  = (const float*)d_in[6];
    const float* lnb  = (const float*)d_in[7];
    float* dout = (float*)d_out;

    k_init<<<1, 1>>>();
    k_wq<<<HD, 256>>>(w, bias, hssf);
    k_pack<<<(ROWS*KW + 255)/256, 256>>>(hs, hssf, inp, insf);
    k_gemm<<<dim3(HD/64, ROWS/64), 256>>>(insf);
    k_prep22<<<1, 768>>>(insf, lnw, lnb);
    k_ln1<<<ROWS, 256>>>();
    k_ln2<<<ROWS, 256>>>();
    k_prep8<<<1, 768>>>(dout, out_size > NTOT ? 1 : 0);
    k_final<<<(NTOT/4 + 255)/256, 256>>>(dout);
}